// round 6
// baseline (speedup 1.0000x reference)
#include <cuda_runtime.h>
#include <cuda_bf16.h>
#include <math.h>

// Problem constants
#define BATCH 2
#define SEQ 4096
#define DMODEL 512
#define NHEADS 8
#define HD 64
#define WINDOW 256
#define MROWS (BATCH * SEQ)       // 8192
#define QKV_N (3 * DMODEL)        // 1536

// Scratch buffers (device globals — no allocation allowed)
__device__ float g_qkv[MROWS * QKV_N];    // [8192, 1536]
__device__ float g_attn[MROWS * DMODEL];  // [8192, 512]

// ---------------------------------------------------------------------------
// TF32 tensor-core NT GEMM with bias (3xTF32 precision scheme):
//   C[M,N] = A[M,K] @ B[N,K]^T + bias[N]
// Block tile 128x128x16, 8 warps (4m x 2n), warp tile 32x64.
// Each input element is split a = a_hi + a_lo (tf32 rounding) ONCE in the
// SMEM loader; mainloop does hi*hi + lo*hi + hi*lo via mma.sync.m16n8k8.tf32.
// M, N multiples of 128; K multiple of 16.
// ---------------------------------------------------------------------------
#define BM 128
#define BN 128
#define BK 16
#define PADK 20   // 20*r mod 32 has order 8 -> conflict-free fragment LDS

__device__ __forceinline__ float f2tf32(float v) {
    unsigned u;
    asm("cvt.rna.tf32.f32 %0, %1;" : "=r"(u) : "f"(v));
    return __uint_as_float(u);
}

__device__ __forceinline__ void split4(float4 v, float4& hi, float4& lo) {
    hi.x = f2tf32(v.x); lo.x = f2tf32(v.x - hi.x);
    hi.y = f2tf32(v.y); lo.y = f2tf32(v.y - hi.y);
    hi.z = f2tf32(v.z); lo.z = f2tf32(v.z - hi.z);
    hi.w = f2tf32(v.w); lo.w = f2tf32(v.w - hi.w);
}

__device__ __forceinline__ void mma_tf32(float c[4], const float a[4], const float b[2]) {
    asm volatile(
        "mma.sync.aligned.m16n8k8.row.col.f32.tf32.tf32.f32 "
        "{%0,%1,%2,%3}, {%4,%5,%6,%7}, {%8,%9}, {%0,%1,%2,%3};"
        : "+f"(c[0]), "+f"(c[1]), "+f"(c[2]), "+f"(c[3])
        : "r"(__float_as_uint(a[0])), "r"(__float_as_uint(a[1])),
          "r"(__float_as_uint(a[2])), "r"(__float_as_uint(a[3])),
          "r"(__float_as_uint(b[0])), "r"(__float_as_uint(b[1])));
}

__global__ __launch_bounds__(256)
void gemm_tf32_bias(const float* __restrict__ A,
                    const float* __restrict__ Bw,
                    const float* __restrict__ bias,
                    float* __restrict__ C,
                    int M, int N, int K)
{
    __shared__ float Ah[BM][PADK];
    __shared__ float Al[BM][PADK];
    __shared__ float Bh[BN][PADK];
    __shared__ float Bl[BN][PADK];

    const int tid  = threadIdx.x;
    const int warp = tid >> 5;
    const int lane = tid & 31;
    const int g    = lane >> 2;   // groupID (0..7)
    const int t    = lane & 3;    // thread-in-group (0..3)
    const int wm   = warp & 3;    // 4 m-warps
    const int wn   = warp >> 2;   // 2 n-warps
    const int m0   = blockIdx.y * BM;
    const int n0   = blockIdx.x * BN;

    // loader mapping: 2 float4 per thread for A, 2 for B, per 16-k slab
    const int lrow0 = tid >> 2;            // 0..63
    const int lrow1 = lrow0 + 64;          // 64..127
    const int lc    = (tid & 3) * 4;       // 0,4,8,12

    const float* aptr0 = A  + (size_t)(m0 + lrow0) * K + lc;
    const float* aptr1 = A  + (size_t)(m0 + lrow1) * K + lc;
    const float* bptr0 = Bw + (size_t)(n0 + lrow0) * K + lc;
    const float* bptr1 = Bw + (size_t)(n0 + lrow1) * K + lc;

    float c[2][8][4];
#pragma unroll
    for (int i = 0; i < 2; i++)
#pragma unroll
        for (int j = 0; j < 8; j++)
#pragma unroll
            for (int r = 0; r < 4; r++) c[i][j][r] = 0.0f;

    float4 a40 = *(const float4*)aptr0;
    float4 a41 = *(const float4*)aptr1;
    float4 b40 = *(const float4*)bptr0;
    float4 b41 = *(const float4*)bptr1;

    for (int k0 = 0; k0 < K; k0 += BK) {
        __syncthreads();   // previous slab fully consumed
        {
            float4 h, l;
            split4(a40, h, l);
            *(float4*)&Ah[lrow0][lc] = h; *(float4*)&Al[lrow0][lc] = l;
            split4(a41, h, l);
            *(float4*)&Ah[lrow1][lc] = h; *(float4*)&Al[lrow1][lc] = l;
            split4(b40, h, l);
            *(float4*)&Bh[lrow0][lc] = h; *(float4*)&Bl[lrow0][lc] = l;
            split4(b41, h, l);
            *(float4*)&Bh[lrow1][lc] = h; *(float4*)&Bl[lrow1][lc] = l;
        }
        __syncthreads();

        if (k0 + BK < K) {
            a40 = *(const float4*)(aptr0 + k0 + BK);
            a41 = *(const float4*)(aptr1 + k0 + BK);
            b40 = *(const float4*)(bptr0 + k0 + BK);
            b41 = *(const float4*)(bptr1 + k0 + BK);
        }

#pragma unroll
        for (int k8 = 0; k8 < BK; k8 += 8) {
            // A fragments (2 m-atoms), hi and lo
            float ah[2][4], al[2][4];
#pragma unroll
            for (int ma = 0; ma < 2; ma++) {
                const int r0 = wm * 32 + ma * 16 + g;
                ah[ma][0] = Ah[r0    ][k8 + t];
                ah[ma][1] = Ah[r0 + 8][k8 + t];
                ah[ma][2] = Ah[r0    ][k8 + t + 4];
                ah[ma][3] = Ah[r0 + 8][k8 + t + 4];
                al[ma][0] = Al[r0    ][k8 + t];
                al[ma][1] = Al[r0 + 8][k8 + t];
                al[ma][2] = Al[r0    ][k8 + t + 4];
                al[ma][3] = Al[r0 + 8][k8 + t + 4];
            }
            // B fragments (8 n-atoms), hi and lo
            float bh[8][2], bl[8][2];
#pragma unroll
            for (int na = 0; na < 8; na++) {
                const int rn = wn * 64 + na * 8 + g;
                bh[na][0] = Bh[rn][k8 + t];
                bh[na][1] = Bh[rn][k8 + t + 4];
                bl[na][0] = Bl[rn][k8 + t];
                bl[na][1] = Bl[rn][k8 + t + 4];
            }
#pragma unroll
            for (int ma = 0; ma < 2; ma++)
#pragma unroll
                for (int na = 0; na < 8; na++) {
                    mma_tf32(c[ma][na], ah[ma], bh[na]);
                    mma_tf32(c[ma][na], al[ma], bh[na]);
                    mma_tf32(c[ma][na], ah[ma], bl[na]);
                }
        }
    }

    // epilogue: bias + float2 stores
#pragma unroll
    for (int ma = 0; ma < 2; ma++) {
        const int row = m0 + wm * 32 + ma * 16 + g;
#pragma unroll
        for (int na = 0; na < 8; na++) {
            const int col = n0 + wn * 64 + na * 8 + t * 2;
            float2 bv = *(const float2*)&bias[col];
            float2 r0, r1;
            r0.x = c[ma][na][0] + bv.x; r0.y = c[ma][na][1] + bv.y;
            r1.x = c[ma][na][2] + bv.x; r1.y = c[ma][na][3] + bv.y;
            *(float2*)&C[(size_t)row * N + col]       = r0;
            *(float2*)&C[(size_t)(row + 8) * N + col] = r1;
        }
    }
}

// ---------------------------------------------------------------------------
// Sliding-window attention (flash-style online softmax) — unchanged from R4.
// ---------------------------------------------------------------------------
#define QT 32
#define KT 32
#define PAD 68

__global__ __launch_bounds__(256)
void attn_window_kernel(const float* __restrict__ qkv,
                        float* __restrict__ attn_out)
{
    __shared__ float Qs[QT][PAD];
    __shared__ float Ks[KT][PAD];
    __shared__ float Vs[KT][PAD];
    __shared__ float Ps[8][4][KT];   // [warp][qi][key]

    const int b     = blockIdx.z;
    const int h     = blockIdx.y;
    const int qbase = blockIdx.x * QT;
    const int tid   = threadIdx.x;
    const int warp  = tid >> 5;
    const int lane  = tid & 31;

    const float scale = 0.125f;  // 1/sqrt(64)

    for (int i = tid; i < QT * HD / 4; i += 256) {
        int r = i >> 4, c = (i & 15) * 4;
        float4 v = *(const float4*)&qkv[(size_t)(b * SEQ + qbase + r) * QKV_N + h * HD + c];
        *(float4*)&Qs[r][c] = v;
    }

    float ox[4], oy[4], m[4], l[4];
#pragma unroll
    for (int qi = 0; qi < 4; qi++) {
        ox[qi] = 0.f; oy[qi] = 0.f; m[qi] = -1e30f; l[qi] = 0.f;
    }

    int jstart = qbase - WINDOW;
    if (jstart < 0) jstart = 0;
    const int jend = qbase + QT;
    const int qr = warp * 4;

    for (int j0 = jstart; j0 < jend; j0 += KT) {
        __syncthreads();
        for (int i = tid; i < KT * HD / 4; i += 256) {
            int r = i >> 4, c = (i & 15) * 4;
            size_t base = (size_t)(b * SEQ + j0 + r) * QKV_N + h * HD + c;
            float4 kv = *(const float4*)&qkv[base + DMODEL];
            float4 vv = *(const float4*)&qkv[base + 2 * DMODEL];
            *(float4*)&Ks[r][c] = kv;
            *(float4*)&Vs[r][c] = vv;
        }
        __syncthreads();

        // ---- score phase: lane = key, 4 queries at once ----
        float s[4] = {0.f, 0.f, 0.f, 0.f};
        const float4* kp = (const float4*)&Ks[lane][0];
#pragma unroll
        for (int d4 = 0; d4 < 16; d4++) {
            float4 kv = kp[d4];
            float4 q0 = *(const float4*)&Qs[qr + 0][d4 * 4];
            float4 q1 = *(const float4*)&Qs[qr + 1][d4 * 4];
            float4 q2 = *(const float4*)&Qs[qr + 2][d4 * 4];
            float4 q3 = *(const float4*)&Qs[qr + 3][d4 * 4];
            s[0] = fmaf(kv.x, q0.x, s[0]); s[0] = fmaf(kv.y, q0.y, s[0]);
            s[0] = fmaf(kv.z, q0.z, s[0]); s[0] = fmaf(kv.w, q0.w, s[0]);
            s[1] = fmaf(kv.x, q1.x, s[1]); s[1] = fmaf(kv.y, q1.y, s[1]);
            s[1] = fmaf(kv.z, q1.z, s[1]); s[1] = fmaf(kv.w, q1.w, s[1]);
            s[2] = fmaf(kv.x, q2.x, s[2]); s[2] = fmaf(kv.y, q2.y, s[2]);
            s[2] = fmaf(kv.z, q2.z, s[2]); s[2] = fmaf(kv.w, q2.w, s[2]);
            s[3] = fmaf(kv.x, q3.x, s[3]); s[3] = fmaf(kv.y, q3.y, s[3]);
            s[3] = fmaf(kv.z, q3.z, s[3]); s[3] = fmaf(kv.w, q3.w, s[3]);
        }

        const int j = j0 + lane;
#pragma unroll
        for (int qi = 0; qi < 4; qi++) {
            const int q = qbase + qr + qi;
            float sv = s[qi] * scale;
            const bool valid = (j <= q) && (j >= q - WINDOW);
            sv = valid ? sv : -1e30f;

            float mc = sv;
#pragma unroll
            for (int o = 16; o; o >>= 1)
                mc = fmaxf(mc, __shfl_xor_sync(0xffffffffu, mc, o));
            const float mnew  = fmaxf(m[qi], mc);
            const float p     = __expf(sv - mnew);
            const float alpha = __expf(m[qi] - mnew);
            m[qi] = mnew;

            float ps = p;
#pragma unroll
            for (int o = 16; o; o >>= 1)
                ps += __shfl_xor_sync(0xffffffffu, ps, o);
            l[qi]  = l[qi] * alpha + ps;
            ox[qi] *= alpha;
            oy[qi] *= alpha;
            Ps[warp][qi][lane] = p;
        }
        __syncwarp();

        // ---- PV phase: lane = dim pair ----
#pragma unroll
        for (int jj = 0; jj < KT; jj += 4) {
            float2 v0 = *(const float2*)&Vs[jj + 0][lane * 2];
            float2 v1 = *(const float2*)&Vs[jj + 1][lane * 2];
            float2 v2 = *(const float2*)&Vs[jj + 2][lane * 2];
            float2 v3 = *(const float2*)&Vs[jj + 3][lane * 2];
#pragma unroll
            for (int qi = 0; qi < 4; qi++) {
                float4 p4 = *(const float4*)&Ps[warp][qi][jj];
                ox[qi] = fmaf(p4.x, v0.x, ox[qi]);
                ox[qi] = fmaf(p4.y, v1.x, ox[qi]);
                ox[qi] = fmaf(p4.z, v2.x, ox[qi]);
                ox[qi] = fmaf(p4.w, v3.x, ox[qi]);
                oy[qi] = fmaf(p4.x, v0.y, oy[qi]);
                oy[qi] = fmaf(p4.y, v1.y, oy[qi]);
                oy[qi] = fmaf(p4.z, v2.y, oy[qi]);
                oy[qi] = fmaf(p4.w, v3.y, oy[qi]);
            }
        }
    }

#pragma unroll
    for (int qi = 0; qi < 4; qi++) {
        const int q = qbase + qr + qi;
        const float inv = 1.0f / l[qi];
        float2 r;
        r.x = ox[qi] * inv;
        r.y = oy[qi] * inv;
        *(float2*)&attn_out[(size_t)(b * SEQ + q) * DMODEL + h * HD + lane * 2] = r;
    }
}

// ---------------------------------------------------------------------------
// kernel_launch
// ---------------------------------------------------------------------------
extern "C" void kernel_launch(void* const* d_in, const int* in_sizes, int n_in,
                              void* d_out, int out_size)
{
    const float* x     = (const float*)d_in[0];
    const float* qkv_w = (const float*)d_in[1];
    const float* qkv_b = (const float*)d_in[2];
    const float* out_w = (const float*)d_in[3];
    const float* out_b = (const float*)d_in[4];
    float* out = (float*)d_out;

    float* qkv_buf;  cudaGetSymbolAddress((void**)&qkv_buf,  g_qkv);
    float* attn_buf; cudaGetSymbolAddress((void**)&attn_buf, g_attn);

    // 1) QKV projection: [8192,512] @ [512,1536] + bias (tensor cores, 3xTF32)
    {
        dim3 grid(QKV_N / BN, MROWS / BM);
        gemm_tf32_bias<<<grid, 256>>>(x, qkv_w, qkv_b, qkv_buf,
                                      MROWS, QKV_N, DMODEL);
    }

    // 2) Sliding-window attention
    {
        dim3 grid(SEQ / QT, NHEADS, BATCH);
        attn_window_kernel<<<grid, 256>>>(qkv_buf, attn_buf);
    }

    // 3) Output projection: [8192,512] @ [512,512] + bias (tensor cores, 3xTF32)
    {
        dim3 grid(DMODEL / BN, MROWS / BM);
        gemm_tf32_bias<<<grid, 256>>>(attn_buf, out_w, out_b, out,
                                      MROWS, DMODEL, DMODEL);
    }
}

// round 7
// speedup vs baseline: 1.2628x; 1.2628x over previous
#include <cuda_runtime.h>
#include <cuda_bf16.h>
#include <math.h>
#include <stdint.h>

// Problem constants
#define BATCH 2
#define SEQ 4096
#define DMODEL 512
#define NHEADS 8
#define HD 64
#define WINDOW 256
#define MROWS (BATCH * SEQ)       // 8192
#define QKV_N (3 * DMODEL)        // 1536

// Scratch buffers (device globals — no allocation allowed)
__device__ float g_qkv[MROWS * QKV_N];    // [8192, 1536]
__device__ float g_attn[MROWS * DMODEL];  // [8192, 512]

// ---------------------------------------------------------------------------
// Split-bf16 tensor-core NT GEMM with bias:
//   C[M,N] = A[M,K] @ B[N,K]^T + bias[N]
// a = a_hi + a_lo (bf16 each); C ≈ ah*bh + al*bh + ah*bl  (al*bl ~2^-18 dropped)
// mma.sync.m16n8k16.bf16. Block tile 128x128x32, 8 warps (4m x 2n),
// warp tile 32x64. SMEM holds bf16x2-packed hi/lo tiles, row stride 20 u32
// (conflict-free fragment LDS: g*20+t mod 32 is a permutation).
// M, N multiples of 128; K multiple of 32.
// ---------------------------------------------------------------------------
#define BM 128
#define BN 128
#define BK 32
#define PSTR 20   // uint32 stride per row (16 data + 4 pad)

__device__ __forceinline__ void f4_to_bf16x2(float4 v,
                                             uint32_t& h0, uint32_t& h1,
                                             uint32_t& l0, uint32_t& l1)
{
    __nv_bfloat16 hx = __float2bfloat16(v.x), hy = __float2bfloat16(v.y);
    __nv_bfloat16 hz = __float2bfloat16(v.z), hw = __float2bfloat16(v.w);
    __nv_bfloat16 lx = __float2bfloat16(v.x - __bfloat162float(hx));
    __nv_bfloat16 ly = __float2bfloat16(v.y - __bfloat162float(hy));
    __nv_bfloat16 lz = __float2bfloat16(v.z - __bfloat162float(hz));
    __nv_bfloat16 lw = __float2bfloat16(v.w - __bfloat162float(hw));
    __nv_bfloat162 H0 = __halves2bfloat162(hx, hy);
    __nv_bfloat162 H1 = __halves2bfloat162(hz, hw);
    __nv_bfloat162 L0 = __halves2bfloat162(lx, ly);
    __nv_bfloat162 L1 = __halves2bfloat162(lz, lw);
    h0 = *reinterpret_cast<uint32_t*>(&H0);
    h1 = *reinterpret_cast<uint32_t*>(&H1);
    l0 = *reinterpret_cast<uint32_t*>(&L0);
    l1 = *reinterpret_cast<uint32_t*>(&L1);
}

__device__ __forceinline__ void mma_bf16(float c[4], const uint32_t a[4], const uint32_t b[2]) {
    asm volatile(
        "mma.sync.aligned.m16n8k16.row.col.f32.bf16.bf16.f32 "
        "{%0,%1,%2,%3}, {%4,%5,%6,%7}, {%8,%9}, {%0,%1,%2,%3};"
        : "+f"(c[0]), "+f"(c[1]), "+f"(c[2]), "+f"(c[3])
        : "r"(a[0]), "r"(a[1]), "r"(a[2]), "r"(a[3]),
          "r"(b[0]), "r"(b[1]));
}

__global__ __launch_bounds__(256)
void gemm_bf16split_bias(const float* __restrict__ A,
                         const float* __restrict__ Bw,
                         const float* __restrict__ bias,
                         float* __restrict__ C,
                         int M, int N, int K)
{
    __shared__ uint32_t Ah[BM][PSTR];
    __shared__ uint32_t Al[BM][PSTR];
    __shared__ uint32_t Bh[BN][PSTR];
    __shared__ uint32_t Bl[BN][PSTR];

    const int tid  = threadIdx.x;
    const int warp = tid >> 5;
    const int lane = tid & 31;
    const int g    = lane >> 2;   // groupID 0..7
    const int t    = lane & 3;    // thread-in-group 0..3
    const int wm   = warp & 3;    // 4 m-warps
    const int wn   = warp >> 2;   // 2 n-warps
    const int m0   = blockIdx.y * BM;
    const int n0   = blockIdx.x * BN;

    // loader: each thread owns one row-half (16 consecutive floats) of A and B
    const int lrow  = tid >> 1;        // 0..127
    const int lhalf = tid & 1;         // 0/1 -> k offset 0/16

    const float* aptr = A  + (size_t)(m0 + lrow) * K + lhalf * 16;
    const float* bptr = Bw + (size_t)(n0 + lrow) * K + lhalf * 16;

    float c[2][8][4];
#pragma unroll
    for (int i = 0; i < 2; i++)
#pragma unroll
        for (int j = 0; j < 8; j++)
#pragma unroll
            for (int r = 0; r < 4; r++) c[i][j][r] = 0.0f;

    float4 af[4], bf[4];
#pragma unroll
    for (int i = 0; i < 4; i++) {
        af[i] = *(const float4*)(aptr + i * 4);
        bf[i] = *(const float4*)(bptr + i * 4);
    }

    for (int k0 = 0; k0 < K; k0 += BK) {
        __syncthreads();   // previous slab fully consumed
        {
            uint32_t h[8], l[8];
#pragma unroll
            for (int i = 0; i < 4; i++)
                f4_to_bf16x2(af[i], h[2*i], h[2*i+1], l[2*i], l[2*i+1]);
            *(uint4*)&Ah[lrow][lhalf * 8]     = make_uint4(h[0], h[1], h[2], h[3]);
            *(uint4*)&Ah[lrow][lhalf * 8 + 4] = make_uint4(h[4], h[5], h[6], h[7]);
            *(uint4*)&Al[lrow][lhalf * 8]     = make_uint4(l[0], l[1], l[2], l[3]);
            *(uint4*)&Al[lrow][lhalf * 8 + 4] = make_uint4(l[4], l[5], l[6], l[7]);
#pragma unroll
            for (int i = 0; i < 4; i++)
                f4_to_bf16x2(bf[i], h[2*i], h[2*i+1], l[2*i], l[2*i+1]);
            *(uint4*)&Bh[lrow][lhalf * 8]     = make_uint4(h[0], h[1], h[2], h[3]);
            *(uint4*)&Bh[lrow][lhalf * 8 + 4] = make_uint4(h[4], h[5], h[6], h[7]);
            *(uint4*)&Bl[lrow][lhalf * 8]     = make_uint4(l[0], l[1], l[2], l[3]);
            *(uint4*)&Bl[lrow][lhalf * 8 + 4] = make_uint4(l[4], l[5], l[6], l[7]);
        }
        __syncthreads();

        if (k0 + BK < K) {
#pragma unroll
            for (int i = 0; i < 4; i++) {
                af[i] = *(const float4*)(aptr + k0 + BK + i * 4);
                bf[i] = *(const float4*)(bptr + k0 + BK + i * 4);
            }
        }

#pragma unroll
        for (int s = 0; s < 2; s++) {      // two k16 steps per slab
            const int cb = s * 8 + t;      // uint32 column base

            uint32_t ah[2][4], al[2][4];
#pragma unroll
            for (int ma = 0; ma < 2; ma++) {
                const int r0 = wm * 32 + ma * 16 + g;
                ah[ma][0] = Ah[r0    ][cb];
                ah[ma][1] = Ah[r0 + 8][cb];
                ah[ma][2] = Ah[r0    ][cb + 4];
                ah[ma][3] = Ah[r0 + 8][cb + 4];
                al[ma][0] = Al[r0    ][cb];
                al[ma][1] = Al[r0 + 8][cb];
                al[ma][2] = Al[r0    ][cb + 4];
                al[ma][3] = Al[r0 + 8][cb + 4];
            }
            uint32_t bh[8][2], bl[8][2];
#pragma unroll
            for (int na = 0; na < 8; na++) {
                const int rn = wn * 64 + na * 8 + g;
                bh[na][0] = Bh[rn][cb];
                bh[na][1] = Bh[rn][cb + 4];
                bl[na][0] = Bl[rn][cb];
                bl[na][1] = Bl[rn][cb + 4];
            }
#pragma unroll
            for (int ma = 0; ma < 2; ma++)
#pragma unroll
                for (int na = 0; na < 8; na++) {
                    mma_bf16(c[ma][na], ah[ma], bh[na]);
                    mma_bf16(c[ma][na], al[ma], bh[na]);
                    mma_bf16(c[ma][na], ah[ma], bl[na]);
                }
        }
    }

    // epilogue: bias + float2 stores
    // c0,c1 -> (row g, cols 2t,2t+1); c2,c3 -> (row g+8, cols 2t,2t+1)
#pragma unroll
    for (int ma = 0; ma < 2; ma++) {
        const int row = m0 + wm * 32 + ma * 16 + g;
#pragma unroll
        for (int na = 0; na < 8; na++) {
            const int col = n0 + wn * 64 + na * 8 + t * 2;
            float2 bv = *(const float2*)&bias[col];
            float2 r0, r1;
            r0.x = c[ma][na][0] + bv.x; r0.y = c[ma][na][1] + bv.y;
            r1.x = c[ma][na][2] + bv.x; r1.y = c[ma][na][3] + bv.y;
            *(float2*)&C[(size_t)row * N + col]       = r0;
            *(float2*)&C[(size_t)(row + 8) * N + col] = r1;
        }
    }
}

// ---------------------------------------------------------------------------
// Sliding-window attention (flash-style online softmax) — unchanged from R4/R5.
// ---------------------------------------------------------------------------
#define QT 32
#define KT 32
#define PAD 68

__global__ __launch_bounds__(256)
void attn_window_kernel(const float* __restrict__ qkv,
                        float* __restrict__ attn_out)
{
    __shared__ float Qs[QT][PAD];
    __shared__ float Ks[KT][PAD];
    __shared__ float Vs[KT][PAD];
    __shared__ float Ps[8][4][KT];   // [warp][qi][key]

    const int b     = blockIdx.z;
    const int h     = blockIdx.y;
    const int qbase = blockIdx.x * QT;
    const int tid   = threadIdx.x;
    const int warp  = tid >> 5;
    const int lane  = tid & 31;

    const float scale = 0.125f;  // 1/sqrt(64)

    for (int i = tid; i < QT * HD / 4; i += 256) {
        int r = i >> 4, c = (i & 15) * 4;
        float4 v = *(const float4*)&qkv[(size_t)(b * SEQ + qbase + r) * QKV_N + h * HD + c];
        *(float4*)&Qs[r][c] = v;
    }

    float ox[4], oy[4], m[4], l[4];
#pragma unroll
    for (int qi = 0; qi < 4; qi++) {
        ox[qi] = 0.f; oy[qi] = 0.f; m[qi] = -1e30f; l[qi] = 0.f;
    }

    int jstart = qbase - WINDOW;
    if (jstart < 0) jstart = 0;
    const int jend = qbase + QT;
    const int qr = warp * 4;

    for (int j0 = jstart; j0 < jend; j0 += KT) {
        __syncthreads();
        for (int i = tid; i < KT * HD / 4; i += 256) {
            int r = i >> 4, c = (i & 15) * 4;
            size_t base = (size_t)(b * SEQ + j0 + r) * QKV_N + h * HD + c;
            float4 kv = *(const float4*)&qkv[base + DMODEL];
            float4 vv = *(const float4*)&qkv[base + 2 * DMODEL];
            *(float4*)&Ks[r][c] = kv;
            *(float4*)&Vs[r][c] = vv;
        }
        __syncthreads();

        // ---- score phase: lane = key, 4 queries at once ----
        float s[4] = {0.f, 0.f, 0.f, 0.f};
        const float4* kp = (const float4*)&Ks[lane][0];
#pragma unroll
        for (int d4 = 0; d4 < 16; d4++) {
            float4 kv = kp[d4];
            float4 q0 = *(const float4*)&Qs[qr + 0][d4 * 4];
            float4 q1 = *(const float4*)&Qs[qr + 1][d4 * 4];
            float4 q2 = *(const float4*)&Qs[qr + 2][d4 * 4];
            float4 q3 = *(const float4*)&Qs[qr + 3][d4 * 4];
            s[0] = fmaf(kv.x, q0.x, s[0]); s[0] = fmaf(kv.y, q0.y, s[0]);
            s[0] = fmaf(kv.z, q0.z, s[0]); s[0] = fmaf(kv.w, q0.w, s[0]);
            s[1] = fmaf(kv.x, q1.x, s[1]); s[1] = fmaf(kv.y, q1.y, s[1]);
            s[1] = fmaf(kv.z, q1.z, s[1]); s[1] = fmaf(kv.w, q1.w, s[1]);
            s[2] = fmaf(kv.x, q2.x, s[2]); s[2] = fmaf(kv.y, q2.y, s[2]);
            s[2] = fmaf(kv.z, q2.z, s[2]); s[2] = fmaf(kv.w, q2.w, s[2]);
            s[3] = fmaf(kv.x, q3.x, s[3]); s[3] = fmaf(kv.y, q3.y, s[3]);
            s[3] = fmaf(kv.z, q3.z, s[3]); s[3] = fmaf(kv.w, q3.w, s[3]);
        }

        const int j = j0 + lane;
#pragma unroll
        for (int qi = 0; qi < 4; qi++) {
            const int q = qbase + qr + qi;
            float sv = s[qi] * scale;
            const bool valid = (j <= q) && (j >= q - WINDOW);
            sv = valid ? sv : -1e30f;

            float mc = sv;
#pragma unroll
            for (int o = 16; o; o >>= 1)
                mc = fmaxf(mc, __shfl_xor_sync(0xffffffffu, mc, o));
            const float mnew  = fmaxf(m[qi], mc);
            const float p     = __expf(sv - mnew);
            const float alpha = __expf(m[qi] - mnew);
            m[qi] = mnew;

            float ps = p;
#pragma unroll
            for (int o = 16; o; o >>= 1)
                ps += __shfl_xor_sync(0xffffffffu, ps, o);
            l[qi]  = l[qi] * alpha + ps;
            ox[qi] *= alpha;
            oy[qi] *= alpha;
            Ps[warp][qi][lane] = p;
        }
        __syncwarp();

        // ---- PV phase: lane = dim pair ----
#pragma unroll
        for (int jj = 0; jj < KT; jj += 4) {
            float2 v0 = *(const float2*)&Vs[jj + 0][lane * 2];
            float2 v1 = *(const float2*)&Vs[jj + 1][lane * 2];
            float2 v2 = *(const float2*)&Vs[jj + 2][lane * 2];
            float2 v3 = *(const float2*)&Vs[jj + 3][lane * 2];
#pragma unroll
            for (int qi = 0; qi < 4; qi++) {
                float4 p4 = *(const float4*)&Ps[warp][qi][jj];
                ox[qi] = fmaf(p4.x, v0.x, ox[qi]);
                ox[qi] = fmaf(p4.y, v1.x, ox[qi]);
                ox[qi] = fmaf(p4.z, v2.x, ox[qi]);
                ox[qi] = fmaf(p4.w, v3.x, ox[qi]);
                oy[qi] = fmaf(p4.x, v0.y, oy[qi]);
                oy[qi] = fmaf(p4.y, v1.y, oy[qi]);
                oy[qi] = fmaf(p4.z, v2.y, oy[qi]);
                oy[qi] = fmaf(p4.w, v3.y, oy[qi]);
            }
        }
    }

#pragma unroll
    for (int qi = 0; qi < 4; qi++) {
        const int q = qbase + qr + qi;
        const float inv = 1.0f / l[qi];
        float2 r;
        r.x = ox[qi] * inv;
        r.y = oy[qi] * inv;
        *(float2*)&attn_out[(size_t)(b * SEQ + q) * DMODEL + h * HD + lane * 2] = r;
    }
}

// ---------------------------------------------------------------------------
// kernel_launch
// ---------------------------------------------------------------------------
extern "C" void kernel_launch(void* const* d_in, const int* in_sizes, int n_in,
                              void* d_out, int out_size)
{
    const float* x     = (const float*)d_in[0];
    const float* qkv_w = (const float*)d_in[1];
    const float* qkv_b = (const float*)d_in[2];
    const float* out_w = (const float*)d_in[3];
    const float* out_b = (const float*)d_in[4];
    float* out = (float*)d_out;

    float* qkv_buf;  cudaGetSymbolAddress((void**)&qkv_buf,  g_qkv);
    float* attn_buf; cudaGetSymbolAddress((void**)&attn_buf, g_attn);

    // 1) QKV projection: [8192,512] @ [512,1536] + bias (split-bf16 tensor cores)
    {
        dim3 grid(QKV_N / BN, MROWS / BM);
        gemm_bf16split_bias<<<grid, 256>>>(x, qkv_w, qkv_b, qkv_buf,
                                           MROWS, QKV_N, DMODEL);
    }

    // 2) Sliding-window attention
    {
        dim3 grid(SEQ / QT, NHEADS, BATCH);
        attn_window_kernel<<<grid, 256>>>(qkv_buf, attn_buf);
    }

    // 3) Output projection: [8192,512] @ [512,512] + bias (split-bf16 tensor cores)
    {
        dim3 grid(DMODEL / BN, MROWS / BM);
        gemm_bf16split_bias<<<grid, 256>>>(attn_buf, out_w, out_b, out,
                                           MROWS, DMODEL, DMODEL);
    }
}

// round 8
// speedup vs baseline: 1.3970x; 1.1062x over previous
#include <cuda_runtime.h>
#include <cuda_bf16.h>
#include <math.h>
#include <stdint.h>

// Problem constants
#define BATCH 2
#define SEQ 4096
#define DMODEL 512
#define NHEADS 8
#define HD 64
#define WINDOW 256
#define MROWS (BATCH * SEQ)       // 8192
#define QKV_N (3 * DMODEL)        // 1536

// Scratch buffers (device globals — no allocation allowed)
__device__ float g_qkv[MROWS * QKV_N];    // [8192, 1536]
__device__ float g_attn[MROWS * DMODEL];  // [8192, 512]

// ---------------------------------------------------------------------------
// Split-bf16 tensor-core NT GEMM with bias:
//   C[M,N] = A[M,K] @ B[N,K]^T + bias[N]
// a = a_hi + a_lo (bf16 each); C ≈ ah*bh + al*bh + ah*bl
// mma.sync.m16n8k16.bf16, ldmatrix.x4 fragment loads, 2-stage SMEM pipeline.
// Block tile 128x128x32, 8 warps (4m x 2n), warp tile 32x64.
// SMEM rows stride 20 u32 (LDSM phases hit all 32 banks exactly once).
// M, N multiples of 128; K multiple of 32.
// ---------------------------------------------------------------------------
#define BM 128
#define BN 128
#define BK 32
#define PSTR 20   // uint32 stride per row (16 data + 4 pad)

#define GEMM_SMEM_BYTES (2 * 4 * BM * PSTR * 4)   // 2 stages x 4 tiles = 81920 B

__device__ __forceinline__ void f4_to_bf16x2(float4 v,
                                             uint32_t& h0, uint32_t& h1,
                                             uint32_t& l0, uint32_t& l1)
{
    __nv_bfloat16 hx = __float2bfloat16(v.x), hy = __float2bfloat16(v.y);
    __nv_bfloat16 hz = __float2bfloat16(v.z), hw = __float2bfloat16(v.w);
    __nv_bfloat16 lx = __float2bfloat16(v.x - __bfloat162float(hx));
    __nv_bfloat16 ly = __float2bfloat16(v.y - __bfloat162float(hy));
    __nv_bfloat16 lz = __float2bfloat16(v.z - __bfloat162float(hz));
    __nv_bfloat16 lw = __float2bfloat16(v.w - __bfloat162float(hw));
    __nv_bfloat162 H0 = __halves2bfloat162(hx, hy);
    __nv_bfloat162 H1 = __halves2bfloat162(hz, hw);
    __nv_bfloat162 L0 = __halves2bfloat162(lx, ly);
    __nv_bfloat162 L1 = __halves2bfloat162(lz, lw);
    h0 = *reinterpret_cast<uint32_t*>(&H0);
    h1 = *reinterpret_cast<uint32_t*>(&H1);
    l0 = *reinterpret_cast<uint32_t*>(&L0);
    l1 = *reinterpret_cast<uint32_t*>(&L1);
}

__device__ __forceinline__ void mma_bf16(float c[4], const uint32_t a[4], const uint32_t b[2]) {
    asm volatile(
        "mma.sync.aligned.m16n8k16.row.col.f32.bf16.bf16.f32 "
        "{%0,%1,%2,%3}, {%4,%5,%6,%7}, {%8,%9}, {%0,%1,%2,%3};"
        : "+f"(c[0]), "+f"(c[1]), "+f"(c[2]), "+f"(c[3])
        : "r"(a[0]), "r"(a[1]), "r"(a[2]), "r"(a[3]),
          "r"(b[0]), "r"(b[1]));
}

__device__ __forceinline__ void ldsm_x4(uint32_t r[4], const uint32_t* p) {
    uint32_t addr = (uint32_t)__cvta_generic_to_shared(p);
    asm volatile("ldmatrix.sync.aligned.m8n8.x4.shared.b16 {%0,%1,%2,%3}, [%4];"
                 : "=r"(r[0]), "=r"(r[1]), "=r"(r[2]), "=r"(r[3]) : "r"(addr));
}

__global__ __launch_bounds__(256)
void gemm_bf16split_bias(const float* __restrict__ A,
                         const float* __restrict__ Bw,
                         const float* __restrict__ bias,
                         float* __restrict__ C,
                         int M, int N, int K)
{
    extern __shared__ uint32_t smem_u32[];
    typedef uint32_t Tile[BM][PSTR];
    Tile* Ah = (Tile*)smem_u32;   // [2]
    Tile* Al = Ah + 2;
    Tile* Bh = Al + 2;
    Tile* Bl = Bh + 2;

    const int tid  = threadIdx.x;
    const int warp = tid >> 5;
    const int lane = tid & 31;
    const int wm   = warp & 3;    // 4 m-warps
    const int wn   = warp >> 2;   // 2 n-warps
    const int m0   = blockIdx.y * BM;
    const int n0   = blockIdx.x * BN;

    // ldmatrix per-lane address offsets
    const int a_row = (lane & 7) + ((lane >> 3) & 1) * 8;  // within 16-row atom
    const int a_col = (lane >> 4) * 4;                     // 0 or 4 u32 (k+8 half)
    const int b_row = (lane & 7) + ((lane >> 4) & 1) * 8;  // within 16-row pair
    const int b_col = ((lane >> 3) & 1) * 4;

    // loader: each thread owns one 16-float row-half of A and B
    const int lrow  = tid >> 1;        // 0..127
    const int lhalf = tid & 1;         // 0/1 -> k offset 0/16

    const float* aptr = A  + (size_t)(m0 + lrow) * K + lhalf * 16;
    const float* bptr = Bw + (size_t)(n0 + lrow) * K + lhalf * 16;

    float c[2][8][4];
#pragma unroll
    for (int i = 0; i < 2; i++)
#pragma unroll
        for (int j = 0; j < 8; j++)
#pragma unroll
            for (int r = 0; r < 4; r++) c[i][j][r] = 0.0f;

    float4 af[4], bf[4];
#pragma unroll
    for (int i = 0; i < 4; i++) {
        af[i] = *(const float4*)(aptr + i * 4);
        bf[i] = *(const float4*)(bptr + i * 4);
    }

    const int nslabs = K / BK;

    // store slab 0 into stage 0
    {
        uint32_t h[8], l[8];
#pragma unroll
        for (int i = 0; i < 4; i++)
            f4_to_bf16x2(af[i], h[2*i], h[2*i+1], l[2*i], l[2*i+1]);
        *(uint4*)&Ah[0][lrow][lhalf * 8]     = make_uint4(h[0], h[1], h[2], h[3]);
        *(uint4*)&Ah[0][lrow][lhalf * 8 + 4] = make_uint4(h[4], h[5], h[6], h[7]);
        *(uint4*)&Al[0][lrow][lhalf * 8]     = make_uint4(l[0], l[1], l[2], l[3]);
        *(uint4*)&Al[0][lrow][lhalf * 8 + 4] = make_uint4(l[4], l[5], l[6], l[7]);
#pragma unroll
        for (int i = 0; i < 4; i++)
            f4_to_bf16x2(bf[i], h[2*i], h[2*i+1], l[2*i], l[2*i+1]);
        *(uint4*)&Bh[0][lrow][lhalf * 8]     = make_uint4(h[0], h[1], h[2], h[3]);
        *(uint4*)&Bh[0][lrow][lhalf * 8 + 4] = make_uint4(h[4], h[5], h[6], h[7]);
        *(uint4*)&Bl[0][lrow][lhalf * 8]     = make_uint4(l[0], l[1], l[2], l[3]);
        *(uint4*)&Bl[0][lrow][lhalf * 8 + 4] = make_uint4(l[4], l[5], l[6], l[7]);
    }
    __syncthreads();

    for (int s = 0; s < nslabs; s++) {
        const int st = s & 1;

        // prefetch next slab from gmem (in flight during compute)
        if (s + 1 < nslabs) {
            const int koff = (s + 1) * BK;
#pragma unroll
            for (int i = 0; i < 4; i++) {
                af[i] = *(const float4*)(aptr + koff + i * 4);
                bf[i] = *(const float4*)(bptr + koff + i * 4);
            }
        }

        // compute on stage st: two k16 steps
#pragma unroll
        for (int step = 0; step < 2; step++) {
            const int cb = step * 8;

            uint32_t ah[2][4], al[2][4];
#pragma unroll
            for (int ma = 0; ma < 2; ma++) {
                const int r0 = wm * 32 + ma * 16 + a_row;
                ldsm_x4(ah[ma], &Ah[st][r0][cb + a_col]);
                ldsm_x4(al[ma], &Al[st][r0][cb + a_col]);
            }
            uint32_t bhf[8][2], blf[8][2];
#pragma unroll
            for (int pa = 0; pa < 4; pa++) {
                const int rn = wn * 64 + pa * 16 + b_row;
                uint32_t t4[4];
                ldsm_x4(t4, &Bh[st][rn][cb + b_col]);
                bhf[2*pa][0]   = t4[0]; bhf[2*pa][1]   = t4[1];
                bhf[2*pa+1][0] = t4[2]; bhf[2*pa+1][1] = t4[3];
                ldsm_x4(t4, &Bl[st][rn][cb + b_col]);
                blf[2*pa][0]   = t4[0]; blf[2*pa][1]   = t4[1];
                blf[2*pa+1][0] = t4[2]; blf[2*pa+1][1] = t4[3];
            }
#pragma unroll
            for (int ma = 0; ma < 2; ma++)
#pragma unroll
                for (int na = 0; na < 8; na++) {
                    mma_bf16(c[ma][na], ah[ma], bhf[na]);
                    mma_bf16(c[ma][na], al[ma], bhf[na]);
                    mma_bf16(c[ma][na], ah[ma], blf[na]);
                }
        }

        // convert + store next slab into the other stage (overlaps compute tail)
        if (s + 1 < nslabs) {
            const int nx = st ^ 1;
            uint32_t h[8], l[8];
#pragma unroll
            for (int i = 0; i < 4; i++)
                f4_to_bf16x2(af[i], h[2*i], h[2*i+1], l[2*i], l[2*i+1]);
            *(uint4*)&Ah[nx][lrow][lhalf * 8]     = make_uint4(h[0], h[1], h[2], h[3]);
            *(uint4*)&Ah[nx][lrow][lhalf * 8 + 4] = make_uint4(h[4], h[5], h[6], h[7]);
            *(uint4*)&Al[nx][lrow][lhalf * 8]     = make_uint4(l[0], l[1], l[2], l[3]);
            *(uint4*)&Al[nx][lrow][lhalf * 8 + 4] = make_uint4(l[4], l[5], l[6], l[7]);
#pragma unroll
            for (int i = 0; i < 4; i++)
                f4_to_bf16x2(bf[i], h[2*i], h[2*i+1], l[2*i], l[2*i+1]);
            *(uint4*)&Bh[nx][lrow][lhalf * 8]     = make_uint4(h[0], h[1], h[2], h[3]);
            *(uint4*)&Bh[nx][lrow][lhalf * 8 + 4] = make_uint4(h[4], h[5], h[6], h[7]);
            *(uint4*)&Bl[nx][lrow][lhalf * 8]     = make_uint4(l[0], l[1], l[2], l[3]);
            *(uint4*)&Bl[nx][lrow][lhalf * 8 + 4] = make_uint4(l[4], l[5], l[6], l[7]);
        }
        __syncthreads();
    }

    // epilogue: bias + float2 stores
    const int g = lane >> 2;
    const int t = lane & 3;
#pragma unroll
    for (int ma = 0; ma < 2; ma++) {
        const int row = m0 + wm * 32 + ma * 16 + g;
#pragma unroll
        for (int na = 0; na < 8; na++) {
            const int col = n0 + wn * 64 + na * 8 + t * 2;
            float2 bv = *(const float2*)&bias[col];
            float2 r0, r1;
            r0.x = c[ma][na][0] + bv.x; r0.y = c[ma][na][1] + bv.y;
            r1.x = c[ma][na][2] + bv.x; r1.y = c[ma][na][3] + bv.y;
            *(float2*)&C[(size_t)row * N + col]       = r0;
            *(float2*)&C[(size_t)(row + 8) * N + col] = r1;
        }
    }
}

// ---------------------------------------------------------------------------
// Sliding-window attention (flash-style online softmax) — unchanged.
// ---------------------------------------------------------------------------
#define QT 32
#define KT 32
#define PAD 68

__global__ __launch_bounds__(256)
void attn_window_kernel(const float* __restrict__ qkv,
                        float* __restrict__ attn_out)
{
    __shared__ float Qs[QT][PAD];
    __shared__ float Ks[KT][PAD];
    __shared__ float Vs[KT][PAD];
    __shared__ float Ps[8][4][KT];   // [warp][qi][key]

    const int b     = blockIdx.z;
    const int h     = blockIdx.y;
    const int qbase = blockIdx.x * QT;
    const int tid   = threadIdx.x;
    const int warp  = tid >> 5;
    const int lane  = tid & 31;

    const float scale = 0.125f;  // 1/sqrt(64)

    for (int i = tid; i < QT * HD / 4; i += 256) {
        int r = i >> 4, c = (i & 15) * 4;
        float4 v = *(const float4*)&qkv[(size_t)(b * SEQ + qbase + r) * QKV_N + h * HD + c];
        *(float4*)&Qs[r][c] = v;
    }

    float ox[4], oy[4], m[4], l[4];
#pragma unroll
    for (int qi = 0; qi < 4; qi++) {
        ox[qi] = 0.f; oy[qi] = 0.f; m[qi] = -1e30f; l[qi] = 0.f;
    }

    int jstart = qbase - WINDOW;
    if (jstart < 0) jstart = 0;
    const int jend = qbase + QT;
    const int qr = warp * 4;

    for (int j0 = jstart; j0 < jend; j0 += KT) {
        __syncthreads();
        for (int i = tid; i < KT * HD / 4; i += 256) {
            int r = i >> 4, c = (i & 15) * 4;
            size_t base = (size_t)(b * SEQ + j0 + r) * QKV_N + h * HD + c;
            float4 kv = *(const float4*)&qkv[base + DMODEL];
            float4 vv = *(const float4*)&qkv[base + 2 * DMODEL];
            *(float4*)&Ks[r][c] = kv;
            *(float4*)&Vs[r][c] = vv;
        }
        __syncthreads();

        // ---- score phase: lane = key, 4 queries at once ----
        float s[4] = {0.f, 0.f, 0.f, 0.f};
        const float4* kp = (const float4*)&Ks[lane][0];
#pragma unroll
        for (int d4 = 0; d4 < 16; d4++) {
            float4 kv = kp[d4];
            float4 q0 = *(const float4*)&Qs[qr + 0][d4 * 4];
            float4 q1 = *(const float4*)&Qs[qr + 1][d4 * 4];
            float4 q2 = *(const float4*)&Qs[qr + 2][d4 * 4];
            float4 q3 = *(const float4*)&Qs[qr + 3][d4 * 4];
            s[0] = fmaf(kv.x, q0.x, s[0]); s[0] = fmaf(kv.y, q0.y, s[0]);
            s[0] = fmaf(kv.z, q0.z, s[0]); s[0] = fmaf(kv.w, q0.w, s[0]);
            s[1] = fmaf(kv.x, q1.x, s[1]); s[1] = fmaf(kv.y, q1.y, s[1]);
            s[1] = fmaf(kv.z, q1.z, s[1]); s[1] = fmaf(kv.w, q1.w, s[1]);
            s[2] = fmaf(kv.x, q2.x, s[2]); s[2] = fmaf(kv.y, q2.y, s[2]);
            s[2] = fmaf(kv.z, q2.z, s[2]); s[2] = fmaf(kv.w, q2.w, s[2]);
            s[3] = fmaf(kv.x, q3.x, s[3]); s[3] = fmaf(kv.y, q3.y, s[3]);
            s[3] = fmaf(kv.z, q3.z, s[3]); s[3] = fmaf(kv.w, q3.w, s[3]);
        }

        const int j = j0 + lane;
#pragma unroll
        for (int qi = 0; qi < 4; qi++) {
            const int q = qbase + qr + qi;
            float sv = s[qi] * scale;
            const bool valid = (j <= q) && (j >= q - WINDOW);
            sv = valid ? sv : -1e30f;

            float mc = sv;
#pragma unroll
            for (int o = 16; o; o >>= 1)
                mc = fmaxf(mc, __shfl_xor_sync(0xffffffffu, mc, o));
            const float mnew  = fmaxf(m[qi], mc);
            const float p     = __expf(sv - mnew);
            const float alpha = __expf(m[qi] - mnew);
            m[qi] = mnew;

            float ps = p;
#pragma unroll
            for (int o = 16; o; o >>= 1)
                ps += __shfl_xor_sync(0xffffffffu, ps, o);
            l[qi]  = l[qi] * alpha + ps;
            ox[qi] *= alpha;
            oy[qi] *= alpha;
            Ps[warp][qi][lane] = p;
        }
        __syncwarp();

        // ---- PV phase: lane = dim pair ----
#pragma unroll
        for (int jj = 0; jj < KT; jj += 4) {
            float2 v0 = *(const float2*)&Vs[jj + 0][lane * 2];
            float2 v1 = *(const float2*)&Vs[jj + 1][lane * 2];
            float2 v2 = *(const float2*)&Vs[jj + 2][lane * 2];
            float2 v3 = *(const float2*)&Vs[jj + 3][lane * 2];
#pragma unroll
            for (int qi = 0; qi < 4; qi++) {
                float4 p4 = *(const float4*)&Ps[warp][qi][jj];
                ox[qi] = fmaf(p4.x, v0.x, ox[qi]);
                ox[qi] = fmaf(p4.y, v1.x, ox[qi]);
                ox[qi] = fmaf(p4.z, v2.x, ox[qi]);
                ox[qi] = fmaf(p4.w, v3.x, ox[qi]);
                oy[qi] = fmaf(p4.x, v0.y, oy[qi]);
                oy[qi] = fmaf(p4.y, v1.y, oy[qi]);
                oy[qi] = fmaf(p4.z, v2.y, oy[qi]);
                oy[qi] = fmaf(p4.w, v3.y, oy[qi]);
            }
        }
    }

#pragma unroll
    for (int qi = 0; qi < 4; qi++) {
        const int q = qbase + qr + qi;
        const float inv = 1.0f / l[qi];
        float2 r;
        r.x = ox[qi] * inv;
        r.y = oy[qi] * inv;
        *(float2*)&attn_out[(size_t)(b * SEQ + q) * DMODEL + h * HD + lane * 2] = r;
    }
}

// ---------------------------------------------------------------------------
// kernel_launch
// ---------------------------------------------------------------------------
extern "C" void kernel_launch(void* const* d_in, const int* in_sizes, int n_in,
                              void* d_out, int out_size)
{
    const float* x     = (const float*)d_in[0];
    const float* qkv_w = (const float*)d_in[1];
    const float* qkv_b = (const float*)d_in[2];
    const float* out_w = (const float*)d_in[3];
    const float* out_b = (const float*)d_in[4];
    float* out = (float*)d_out;

    float* qkv_buf;  cudaGetSymbolAddress((void**)&qkv_buf,  g_qkv);
    float* attn_buf; cudaGetSymbolAddress((void**)&attn_buf, g_attn);

    // allow 80KB dynamic smem (idempotent host-side attribute set; not a stream op)
    cudaFuncSetAttribute(gemm_bf16split_bias,
                         cudaFuncAttributeMaxDynamicSharedMemorySize,
                         GEMM_SMEM_BYTES);

    // 1) QKV projection: [8192,512] @ [512,1536] + bias (split-bf16 tensor cores)
    {
        dim3 grid(QKV_N / BN, MROWS / BM);
        gemm_bf16split_bias<<<grid, 256, GEMM_SMEM_BYTES>>>(x, qkv_w, qkv_b, qkv_buf,
                                                            MROWS, QKV_N, DMODEL);
    }

    // 2) Sliding-window attention
    {
        dim3 grid(SEQ / QT, NHEADS, BATCH);
        attn_window_kernel<<<grid, 256>>>(qkv_buf, attn_buf);
    }

    // 3) Output projection: [8192,512] @ [512,512] + bias (split-bf16 tensor cores)
    {
        dim3 grid(DMODEL / BN, MROWS / BM);
        gemm_bf16split_bias<<<grid, 256, GEMM_SMEM_BYTES>>>(attn_buf, out_w, out_b, out,
                                                            MROWS, DMODEL, DMODEL);
    }
}

// round 9
// speedup vs baseline: 2.0888x; 1.4952x over previous
#include <cuda_runtime.h>
#include <cuda_bf16.h>
#include <math.h>
#include <stdint.h>

// Problem constants
#define BATCH 2
#define SEQ 4096
#define DMODEL 512
#define NHEADS 8
#define HD 64
#define WINDOW 256
#define MROWS (BATCH * SEQ)       // 8192
#define QKV_N (3 * DMODEL)        // 1536

// Scratch buffers (device globals — no allocation allowed)
__device__ float g_qkv[MROWS * QKV_N];    // [8192, 1536]
__device__ float g_attn[MROWS * DMODEL];  // [8192, 512]

// ---------------------------------------------------------------------------
// Shared helpers: split-bf16 packing, mma, ldmatrix
// ---------------------------------------------------------------------------
__device__ __forceinline__ void f4_to_bf16x2(float4 v,
                                             uint32_t& h0, uint32_t& h1,
                                             uint32_t& l0, uint32_t& l1)
{
    __nv_bfloat16 hx = __float2bfloat16(v.x), hy = __float2bfloat16(v.y);
    __nv_bfloat16 hz = __float2bfloat16(v.z), hw = __float2bfloat16(v.w);
    __nv_bfloat16 lx = __float2bfloat16(v.x - __bfloat162float(hx));
    __nv_bfloat16 ly = __float2bfloat16(v.y - __bfloat162float(hy));
    __nv_bfloat16 lz = __float2bfloat16(v.z - __bfloat162float(hz));
    __nv_bfloat16 lw = __float2bfloat16(v.w - __bfloat162float(hw));
    __nv_bfloat162 H0 = __halves2bfloat162(hx, hy);
    __nv_bfloat162 H1 = __halves2bfloat162(hz, hw);
    __nv_bfloat162 L0 = __halves2bfloat162(lx, ly);
    __nv_bfloat162 L1 = __halves2bfloat162(lz, lw);
    h0 = *reinterpret_cast<uint32_t*>(&H0);
    h1 = *reinterpret_cast<uint32_t*>(&H1);
    l0 = *reinterpret_cast<uint32_t*>(&L0);
    l1 = *reinterpret_cast<uint32_t*>(&L1);
}

__device__ __forceinline__ void split_pack2(float x, float y, uint32_t& hi, uint32_t& lo) {
    __nv_bfloat16 hx = __float2bfloat16(x), hy = __float2bfloat16(y);
    __nv_bfloat16 lx = __float2bfloat16(x - __bfloat162float(hx));
    __nv_bfloat16 ly = __float2bfloat16(y - __bfloat162float(hy));
    __nv_bfloat162 H = __halves2bfloat162(hx, hy);
    __nv_bfloat162 L = __halves2bfloat162(lx, ly);
    hi = *reinterpret_cast<uint32_t*>(&H);
    lo = *reinterpret_cast<uint32_t*>(&L);
}

__device__ __forceinline__ void mma_bf16(float c[4], const uint32_t a[4], const uint32_t b[2]) {
    asm volatile(
        "mma.sync.aligned.m16n8k16.row.col.f32.bf16.bf16.f32 "
        "{%0,%1,%2,%3}, {%4,%5,%6,%7}, {%8,%9}, {%0,%1,%2,%3};"
        : "+f"(c[0]), "+f"(c[1]), "+f"(c[2]), "+f"(c[3])
        : "r"(a[0]), "r"(a[1]), "r"(a[2]), "r"(a[3]),
          "r"(b[0]), "r"(b[1]));
}

__device__ __forceinline__ void ldsm_x4(uint32_t r[4], const uint32_t* p) {
    uint32_t addr = (uint32_t)__cvta_generic_to_shared(p);
    asm volatile("ldmatrix.sync.aligned.m8n8.x4.shared.b16 {%0,%1,%2,%3}, [%4];"
                 : "=r"(r[0]), "=r"(r[1]), "=r"(r[2]), "=r"(r[3]) : "r"(addr));
}

__device__ __forceinline__ void ldsm_x4_t(uint32_t r[4], const uint32_t* p) {
    uint32_t addr = (uint32_t)__cvta_generic_to_shared(p);
    asm volatile("ldmatrix.sync.aligned.m8n8.x4.trans.shared.b16 {%0,%1,%2,%3}, [%4];"
                 : "=r"(r[0]), "=r"(r[1]), "=r"(r[2]), "=r"(r[3]) : "r"(addr));
}

// ---------------------------------------------------------------------------
// Split-bf16 tensor-core NT GEMM with bias (unchanged from R7).
// ---------------------------------------------------------------------------
#define BM 128
#define BN 128
#define BK 32
#define PSTR 20

#define GEMM_SMEM_BYTES (2 * 4 * BM * PSTR * 4)   // 81920 B

__global__ __launch_bounds__(256)
void gemm_bf16split_bias(const float* __restrict__ A,
                         const float* __restrict__ Bw,
                         const float* __restrict__ bias,
                         float* __restrict__ C,
                         int M, int N, int K)
{
    extern __shared__ uint32_t smem_u32[];
    typedef uint32_t Tile[BM][PSTR];
    Tile* Ah = (Tile*)smem_u32;   // [2]
    Tile* Al = Ah + 2;
    Tile* Bh = Al + 2;
    Tile* Bl = Bh + 2;

    const int tid  = threadIdx.x;
    const int warp = tid >> 5;
    const int lane = tid & 31;
    const int wm   = warp & 3;
    const int wn   = warp >> 2;
    const int m0   = blockIdx.y * BM;
    const int n0   = blockIdx.x * BN;

    const int a_row = (lane & 7) + ((lane >> 3) & 1) * 8;
    const int a_col = (lane >> 4) * 4;
    const int b_row = (lane & 7) + ((lane >> 4) & 1) * 8;
    const int b_col = ((lane >> 3) & 1) * 4;

    const int lrow  = tid >> 1;
    const int lhalf = tid & 1;

    const float* aptr = A  + (size_t)(m0 + lrow) * K + lhalf * 16;
    const float* bptr = Bw + (size_t)(n0 + lrow) * K + lhalf * 16;

    float c[2][8][4];
#pragma unroll
    for (int i = 0; i < 2; i++)
#pragma unroll
        for (int j = 0; j < 8; j++)
#pragma unroll
            for (int r = 0; r < 4; r++) c[i][j][r] = 0.0f;

    float4 af[4], bf[4];
#pragma unroll
    for (int i = 0; i < 4; i++) {
        af[i] = *(const float4*)(aptr + i * 4);
        bf[i] = *(const float4*)(bptr + i * 4);
    }

    const int nslabs = K / BK;

    {
        uint32_t h[8], l[8];
#pragma unroll
        for (int i = 0; i < 4; i++)
            f4_to_bf16x2(af[i], h[2*i], h[2*i+1], l[2*i], l[2*i+1]);
        *(uint4*)&Ah[0][lrow][lhalf * 8]     = make_uint4(h[0], h[1], h[2], h[3]);
        *(uint4*)&Ah[0][lrow][lhalf * 8 + 4] = make_uint4(h[4], h[5], h[6], h[7]);
        *(uint4*)&Al[0][lrow][lhalf * 8]     = make_uint4(l[0], l[1], l[2], l[3]);
        *(uint4*)&Al[0][lrow][lhalf * 8 + 4] = make_uint4(l[4], l[5], l[6], l[7]);
#pragma unroll
        for (int i = 0; i < 4; i++)
            f4_to_bf16x2(bf[i], h[2*i], h[2*i+1], l[2*i], l[2*i+1]);
        *(uint4*)&Bh[0][lrow][lhalf * 8]     = make_uint4(h[0], h[1], h[2], h[3]);
        *(uint4*)&Bh[0][lrow][lhalf * 8 + 4] = make_uint4(h[4], h[5], h[6], h[7]);
        *(uint4*)&Bl[0][lrow][lhalf * 8]     = make_uint4(l[0], l[1], l[2], l[3]);
        *(uint4*)&Bl[0][lrow][lhalf * 8 + 4] = make_uint4(l[4], l[5], l[6], l[7]);
    }
    __syncthreads();

    for (int s = 0; s < nslabs; s++) {
        const int st = s & 1;

        if (s + 1 < nslabs) {
            const int koff = (s + 1) * BK;
#pragma unroll
            for (int i = 0; i < 4; i++) {
                af[i] = *(const float4*)(aptr + koff + i * 4);
                bf[i] = *(const float4*)(bptr + koff + i * 4);
            }
        }

#pragma unroll
        for (int step = 0; step < 2; step++) {
            const int cb = step * 8;

            uint32_t ah[2][4], al[2][4];
#pragma unroll
            for (int ma = 0; ma < 2; ma++) {
                const int r0 = wm * 32 + ma * 16 + a_row;
                ldsm_x4(ah[ma], &Ah[st][r0][cb + a_col]);
                ldsm_x4(al[ma], &Al[st][r0][cb + a_col]);
            }
            uint32_t bhf[8][2], blf[8][2];
#pragma unroll
            for (int pa = 0; pa < 4; pa++) {
                const int rn = wn * 64 + pa * 16 + b_row;
                uint32_t t4[4];
                ldsm_x4(t4, &Bh[st][rn][cb + b_col]);
                bhf[2*pa][0]   = t4[0]; bhf[2*pa][1]   = t4[1];
                bhf[2*pa+1][0] = t4[2]; bhf[2*pa+1][1] = t4[3];
                ldsm_x4(t4, &Bl[st][rn][cb + b_col]);
                blf[2*pa][0]   = t4[0]; blf[2*pa][1]   = t4[1];
                blf[2*pa+1][0] = t4[2]; blf[2*pa+1][1] = t4[3];
            }
#pragma unroll
            for (int ma = 0; ma < 2; ma++)
#pragma unroll
                for (int na = 0; na < 8; na++) {
                    mma_bf16(c[ma][na], ah[ma], bhf[na]);
                    mma_bf16(c[ma][na], al[ma], bhf[na]);
                    mma_bf16(c[ma][na], ah[ma], blf[na]);
                }
        }

        if (s + 1 < nslabs) {
            const int nx = st ^ 1;
            uint32_t h[8], l[8];
#pragma unroll
            for (int i = 0; i < 4; i++)
                f4_to_bf16x2(af[i], h[2*i], h[2*i+1], l[2*i], l[2*i+1]);
            *(uint4*)&Ah[nx][lrow][lhalf * 8]     = make_uint4(h[0], h[1], h[2], h[3]);
            *(uint4*)&Ah[nx][lrow][lhalf * 8 + 4] = make_uint4(h[4], h[5], h[6], h[7]);
            *(uint4*)&Al[nx][lrow][lhalf * 8]     = make_uint4(l[0], l[1], l[2], l[3]);
            *(uint4*)&Al[nx][lrow][lhalf * 8 + 4] = make_uint4(l[4], l[5], l[6], l[7]);
#pragma unroll
            for (int i = 0; i < 4; i++)
                f4_to_bf16x2(bf[i], h[2*i], h[2*i+1], l[2*i], l[2*i+1]);
            *(uint4*)&Bh[nx][lrow][lhalf * 8]     = make_uint4(h[0], h[1], h[2], h[3]);
            *(uint4*)&Bh[nx][lrow][lhalf * 8 + 4] = make_uint4(h[4], h[5], h[6], h[7]);
            *(uint4*)&Bl[nx][lrow][lhalf * 8]     = make_uint4(l[0], l[1], l[2], l[3]);
            *(uint4*)&Bl[nx][lrow][lhalf * 8 + 4] = make_uint4(l[4], l[5], l[6], l[7]);
        }
        __syncthreads();
    }

    const int g = lane >> 2;
    const int t = lane & 3;
#pragma unroll
    for (int ma = 0; ma < 2; ma++) {
        const int row = m0 + wm * 32 + ma * 16 + g;
#pragma unroll
        for (int na = 0; na < 8; na++) {
            const int col = n0 + wn * 64 + na * 8 + t * 2;
            float2 bv = *(const float2*)&bias[col];
            float2 r0, r1;
            r0.x = c[ma][na][0] + bv.x; r0.y = c[ma][na][1] + bv.y;
            r1.x = c[ma][na][2] + bv.x; r1.y = c[ma][na][3] + bv.y;
            *(float2*)&C[(size_t)row * N + col]       = r0;
            *(float2*)&C[(size_t)(row + 8) * N + col] = r1;
        }
    }
}

// ---------------------------------------------------------------------------
// Tensor-core sliding-window flash attention (split-bf16, 3-mma scheme).
// Block: 128 threads = 4 warps; 64 queries of one (b, h).
// Warp w owns q-rows [w*16, w*16+16). K tiles of 32 keys.
// QK^T: S(16x32) per warp = 4 k16 steps x 4 n-atoms.
// Softmax: in-register row reduce + shfl over t-lanes. P frags built directly
// from S accumulator registers (C-layout == A-layout for the PV mma).
// PV: P(16x32) x V(32x64), V fragments via ldmatrix.x4.trans on [key][dim].
// ---------------------------------------------------------------------------
#define AQT 64
#define AKT 32
#define ASTR 36   // u32 stride per row (32 data + 4 pad) — LDSM conflict-free

__global__ __launch_bounds__(128)
void attn_mma_kernel(const float* __restrict__ qkv,
                     float* __restrict__ attn_out)
{
    __shared__ uint32_t Qh[AQT][ASTR], Ql[AQT][ASTR];
    __shared__ uint32_t Kh[AKT][ASTR], Kl[AKT][ASTR];
    __shared__ uint32_t Vh[AKT][ASTR], Vl[AKT][ASTR];

    const int b     = blockIdx.z;
    const int h     = blockIdx.y;
    const int qbase = blockIdx.x * AQT;
    const int tid   = threadIdx.x;
    const int warp  = tid >> 5;
    const int lane  = tid & 31;
    const int g     = lane >> 2;
    const int t     = lane & 3;

    // ldmatrix lane offsets
    const int a_row = (lane & 7) + ((lane >> 3) & 1) * 8;
    const int a_col = (lane >> 4) * 4;
    const int b_row = (lane & 7) + ((lane >> 4) & 1) * 8;
    const int b_col = ((lane >> 3) & 1) * 4;
    const int v_row = (lane & 7) + ((lane >> 3) & 1) * 8;
    const int v_col = ((lane >> 4) & 1) * 4;

    // ---- load Q tile (scale folded in), split to bf16 hi/lo ----
    {
        const int r  = tid >> 1;              // 0..63
        const int cf = (tid & 1) * 32;        // float col base
        const float* qp = qkv + (size_t)(b * SEQ + qbase + r) * QKV_N + h * HD + cf;
        uint32_t hh[16], ll[16];
#pragma unroll
        for (int i = 0; i < 8; i++) {
            float4 v = *(const float4*)(qp + i * 4);
            v.x *= 0.125f; v.y *= 0.125f; v.z *= 0.125f; v.w *= 0.125f;
            f4_to_bf16x2(v, hh[2*i], hh[2*i+1], ll[2*i], ll[2*i+1]);
        }
        const int cu = (tid & 1) * 16;        // u32 col base
#pragma unroll
        for (int i = 0; i < 4; i++) {
            *(uint4*)&Qh[r][cu + i * 4] = make_uint4(hh[4*i], hh[4*i+1], hh[4*i+2], hh[4*i+3]);
            *(uint4*)&Ql[r][cu + i * 4] = make_uint4(ll[4*i], ll[4*i+1], ll[4*i+2], ll[4*i+3]);
        }
    }
    __syncthreads();

    // ---- cache Q fragments (reused across all K tiles) ----
    uint32_t qfh[4][4], qfl[4][4];
#pragma unroll
    for (int s = 0; s < 4; s++) {
        ldsm_x4(qfh[s], &Qh[warp * 16 + a_row][s * 8 + a_col]);
        ldsm_x4(qfl[s], &Ql[warp * 16 + a_row][s * 8 + a_col]);
    }

    // per-thread softmax state (rows q0 = base+g and q1 = q0+8)
    float o[8][4];
#pragma unroll
    for (int i = 0; i < 8; i++)
#pragma unroll
        for (int j = 0; j < 4; j++) o[i][j] = 0.0f;
    float m0 = -1e28f, m1 = -1e28f, l0 = 0.0f, l1 = 0.0f;

    const int q0 = qbase + warp * 16 + g;
    const int q1 = q0 + 8;

    int jstart = qbase - WINDOW;
    if (jstart < 0) jstart = 0;
    const int jend = qbase + AQT;

    for (int j0 = jstart; j0 < jend; j0 += AKT) {
        __syncthreads();   // previous tile fully consumed
        // ---- load K/V tile, split to bf16 hi/lo ----
        {
            const int kr = tid >> 2;            // 0..31
            const int cf = (tid & 3) * 16;      // float col base
            const size_t base = (size_t)(b * SEQ + j0 + kr) * QKV_N + h * HD + cf;
            const int cu = (tid & 3) * 8;       // u32 col base
            uint32_t hh[8], ll[8];
#pragma unroll
            for (int i = 0; i < 4; i++) {
                float4 v = *(const float4*)&qkv[base + DMODEL + i * 4];
                f4_to_bf16x2(v, hh[2*i], hh[2*i+1], ll[2*i], ll[2*i+1]);
            }
            *(uint4*)&Kh[kr][cu]     = make_uint4(hh[0], hh[1], hh[2], hh[3]);
            *(uint4*)&Kh[kr][cu + 4] = make_uint4(hh[4], hh[5], hh[6], hh[7]);
            *(uint4*)&Kl[kr][cu]     = make_uint4(ll[0], ll[1], ll[2], ll[3]);
            *(uint4*)&Kl[kr][cu + 4] = make_uint4(ll[4], ll[5], ll[6], ll[7]);
#pragma unroll
            for (int i = 0; i < 4; i++) {
                float4 v = *(const float4*)&qkv[base + 2 * DMODEL + i * 4];
                f4_to_bf16x2(v, hh[2*i], hh[2*i+1], ll[2*i], ll[2*i+1]);
            }
            *(uint4*)&Vh[kr][cu]     = make_uint4(hh[0], hh[1], hh[2], hh[3]);
            *(uint4*)&Vh[kr][cu + 4] = make_uint4(hh[4], hh[5], hh[6], hh[7]);
            *(uint4*)&Vl[kr][cu]     = make_uint4(ll[0], ll[1], ll[2], ll[3]);
            *(uint4*)&Vl[kr][cu + 4] = make_uint4(ll[4], ll[5], ll[6], ll[7]);
        }
        __syncthreads();

        // ---- S = Q K^T (scaled) ----
        float sc[4][4];
#pragma unroll
        for (int na = 0; na < 4; na++)
#pragma unroll
            for (int e = 0; e < 4; e++) sc[na][e] = 0.0f;

#pragma unroll
        for (int s = 0; s < 4; s++) {
            uint32_t kh[4][2], kl[4][2], t4[4];
            ldsm_x4(t4, &Kh[b_row][s * 8 + b_col]);
            kh[0][0] = t4[0]; kh[0][1] = t4[1]; kh[1][0] = t4[2]; kh[1][1] = t4[3];
            ldsm_x4(t4, &Kh[16 + b_row][s * 8 + b_col]);
            kh[2][0] = t4[0]; kh[2][1] = t4[1]; kh[3][0] = t4[2]; kh[3][1] = t4[3];
            ldsm_x4(t4, &Kl[b_row][s * 8 + b_col]);
            kl[0][0] = t4[0]; kl[0][1] = t4[1]; kl[1][0] = t4[2]; kl[1][1] = t4[3];
            ldsm_x4(t4, &Kl[16 + b_row][s * 8 + b_col]);
            kl[2][0] = t4[0]; kl[2][1] = t4[1]; kl[3][0] = t4[2]; kl[3][1] = t4[3];
#pragma unroll
            for (int na = 0; na < 4; na++) {
                mma_bf16(sc[na], qfh[s], kh[na]);
                mma_bf16(sc[na], qfl[s], kh[na]);
                mma_bf16(sc[na], qfh[s], kl[na]);
            }
        }

        // ---- mask (only boundary tiles need it) ----
        const bool nomask = (j0 >= qbase - 192) && (j0 <= qbase - 32);
        if (!nomask) {
#pragma unroll
            for (int na = 0; na < 4; na++) {
                const int c0 = j0 + 8 * na + 2 * t;
                const int c1 = c0 + 1;
                if (c0 > q0 || c0 < q0 - WINDOW) sc[na][0] = -1e30f;
                if (c1 > q0 || c1 < q0 - WINDOW) sc[na][1] = -1e30f;
                if (c0 > q1 || c0 < q1 - WINDOW) sc[na][2] = -1e30f;
                if (c1 > q1 || c1 < q1 - WINDOW) sc[na][3] = -1e30f;
            }
        }

        // ---- online softmax ----
        float mx0 = sc[0][0], mx1 = sc[0][2];
#pragma unroll
        for (int na = 0; na < 4; na++) {
            mx0 = fmaxf(mx0, fmaxf(sc[na][0], sc[na][1]));
            mx1 = fmaxf(mx1, fmaxf(sc[na][2], sc[na][3]));
        }
        mx0 = fmaxf(mx0, __shfl_xor_sync(0xffffffffu, mx0, 1));
        mx0 = fmaxf(mx0, __shfl_xor_sync(0xffffffffu, mx0, 2));
        mx1 = fmaxf(mx1, __shfl_xor_sync(0xffffffffu, mx1, 1));
        mx1 = fmaxf(mx1, __shfl_xor_sync(0xffffffffu, mx1, 2));

        const float mn0 = fmaxf(m0, mx0);
        const float mn1 = fmaxf(m1, mx1);
        const float al0 = __expf(m0 - mn0);
        const float al1 = __expf(m1 - mn1);
        m0 = mn0; m1 = mn1;

        float pv[4][4];
        float s0 = 0.0f, s1 = 0.0f;
#pragma unroll
        for (int na = 0; na < 4; na++) {
            pv[na][0] = __expf(sc[na][0] - mn0);
            pv[na][1] = __expf(sc[na][1] - mn0);
            pv[na][2] = __expf(sc[na][2] - mn1);
            pv[na][3] = __expf(sc[na][3] - mn1);
            s0 += pv[na][0] + pv[na][1];
            s1 += pv[na][2] + pv[na][3];
        }
        s0 += __shfl_xor_sync(0xffffffffu, s0, 1);
        s0 += __shfl_xor_sync(0xffffffffu, s0, 2);
        s1 += __shfl_xor_sync(0xffffffffu, s1, 1);
        s1 += __shfl_xor_sync(0xffffffffu, s1, 2);
        l0 = l0 * al0 + s0;
        l1 = l1 * al1 + s1;

#pragma unroll
        for (int nd = 0; nd < 8; nd++) {
            o[nd][0] *= al0; o[nd][1] *= al0;
            o[nd][2] *= al1; o[nd][3] *= al1;
        }

        // ---- P fragments directly from registers ----
        uint32_t pah[2][4], pal[2][4];
#pragma unroll
        for (int s2 = 0; s2 < 2; s2++) {
            split_pack2(pv[2*s2][0],   pv[2*s2][1],   pah[s2][0], pal[s2][0]);
            split_pack2(pv[2*s2][2],   pv[2*s2][3],   pah[s2][1], pal[s2][1]);
            split_pack2(pv[2*s2+1][0], pv[2*s2+1][1], pah[s2][2], pal[s2][2]);
            split_pack2(pv[2*s2+1][2], pv[2*s2+1][3], pah[s2][3], pal[s2][3]);
        }

        // ---- O += P V ----
#pragma unroll
        for (int s2 = 0; s2 < 2; s2++) {
            uint32_t vbh[8][2], vbl[8][2], t4[4];
#pragma unroll
            for (int db = 0; db < 4; db++) {
                ldsm_x4_t(t4, &Vh[s2 * 16 + v_row][db * 8 + v_col]);
                vbh[2*db][0]   = t4[0]; vbh[2*db][1]   = t4[1];
                vbh[2*db+1][0] = t4[2]; vbh[2*db+1][1] = t4[3];
                ldsm_x4_t(t4, &Vl[s2 * 16 + v_row][db * 8 + v_col]);
                vbl[2*db][0]   = t4[0]; vbl[2*db][1]   = t4[1];
                vbl[2*db+1][0] = t4[2]; vbl[2*db+1][1] = t4[3];
            }
#pragma unroll
            for (int nd = 0; nd < 8; nd++) {
                mma_bf16(o[nd], pah[s2], vbh[nd]);
                mma_bf16(o[nd], pal[s2], vbh[nd]);
                mma_bf16(o[nd], pah[s2], vbl[nd]);
            }
        }
    }

    // ---- normalize + write ----
    const float inv0 = 1.0f / l0;
    const float inv1 = 1.0f / l1;
    float* dst0 = &attn_out[(size_t)(b * SEQ + q0) * DMODEL + h * HD];
    float* dst1 = &attn_out[(size_t)(b * SEQ + q1) * DMODEL + h * HD];
#pragma unroll
    for (int nd = 0; nd < 8; nd++) {
        const int col = 8 * nd + 2 * t;
        float2 r0, r1;
        r0.x = o[nd][0] * inv0; r0.y = o[nd][1] * inv0;
        r1.x = o[nd][2] * inv1; r1.y = o[nd][3] * inv1;
        *(float2*)&dst0[col] = r0;
        *(float2*)&dst1[col] = r1;
    }
}

// ---------------------------------------------------------------------------
// kernel_launch
// ---------------------------------------------------------------------------
extern "C" void kernel_launch(void* const* d_in, const int* in_sizes, int n_in,
                              void* d_out, int out_size)
{
    const float* x     = (const float*)d_in[0];
    const float* qkv_w = (const float*)d_in[1];
    const float* qkv_b = (const float*)d_in[2];
    const float* out_w = (const float*)d_in[3];
    const float* out_b = (const float*)d_in[4];
    float* out = (float*)d_out;

    float* qkv_buf;  cudaGetSymbolAddress((void**)&qkv_buf,  g_qkv);
    float* attn_buf; cudaGetSymbolAddress((void**)&attn_buf, g_attn);

    cudaFuncSetAttribute(gemm_bf16split_bias,
                         cudaFuncAttributeMaxDynamicSharedMemorySize,
                         GEMM_SMEM_BYTES);

    // 1) QKV projection (split-bf16 tensor cores)
    {
        dim3 grid(QKV_N / BN, MROWS / BM);
        gemm_bf16split_bias<<<grid, 256, GEMM_SMEM_BYTES>>>(x, qkv_w, qkv_b, qkv_buf,
                                                            MROWS, QKV_N, DMODEL);
    }

    // 2) Sliding-window attention (split-bf16 tensor cores)
    {
        dim3 grid(SEQ / AQT, NHEADS, BATCH);
        attn_mma_kernel<<<grid, 128>>>(qkv_buf, attn_buf);
    }

    // 3) Output projection (split-bf16 tensor cores)
    {
        dim3 grid(DMODEL / BN, MROWS / BM);
        gemm_bf16split_bias<<<grid, 256, GEMM_SMEM_BYTES>>>(attn_buf, out_w, out_b, out,
                                                            MROWS, DMODEL, DMODEL);
    }
}